// round 10
// baseline (speedup 1.0000x reference)
#include <cuda_runtime.h>

#define BB 256
#define SS 2048
#define KK 64
#define PF 8      // score prefetch depth (steps)
#define HALF 1024 // steps per half-chain

// Scratch (no allocations allowed in kernel_launch)
__device__ float  g_M[KK * KK];   // exp(transition), row i contiguous over j
__device__ float  g_Af[BB * KK];  // forward alpha at t=HALF-1 (scaled)
__device__ float  g_Bb[BB * KK];  // backward beta' at t=HALF-1 (scaled)
__device__ int    g_cf[BB];       // forward exponent offset (log2 units)
__device__ int    g_cb[BB];       // backward exponent offset
__device__ double g_logZ[BB];
__device__ double g_gold[BB];

// ---------- packed f32x2 helpers (Blackwell FFMA2 path, PTX-only) ----------
__device__ __forceinline__ unsigned long long fma2(unsigned long long a,
                                                   unsigned long long b,
                                                   unsigned long long c) {
    unsigned long long d;
    asm("fma.rn.f32x2 %0, %1, %2, %3;" : "=l"(d) : "l"(a), "l"(b), "l"(c));
    return d;
}
__device__ __forceinline__ unsigned long long add2(unsigned long long a,
                                                   unsigned long long b) {
    unsigned long long d;
    asm("add.rn.f32x2 %0, %1, %2;" : "=l"(d) : "l"(a), "l"(b));
    return d;
}
__device__ __forceinline__ float2 unpack2(unsigned long long v) {
    float2 r;
    asm("mov.b64 {%0, %1}, %2;" : "=f"(r.x), "=f"(r.y) : "l"(v));
    return r;
}
__device__ __forceinline__ unsigned long long pack2(float lo, float hi) {
    unsigned long long r;
    asm("mov.b64 %0, {%1, %2};" : "=l"(r) : "f"(lo), "f"(hi));
    return r;
}
__device__ __forceinline__ float warp_sum(float v) {
#pragma unroll
    for (int o = 16; o > 0; o >>= 1)
        v += __shfl_xor_sync(0xffffffffu, v, o);
    return v;
}

// 64-wide matvec partial: sum_i A[i]*Mreg[i] (paired), 4 accumulator chains.
__device__ __forceinline__ float matvec64(const ulonglong2* e4,
                                          const unsigned long long* Mreg) {
    unsigned long long a0 = 0ull, a1 = 0ull, a2 = 0ull, a3 = 0ull;
#pragma unroll
    for (int q = 0; q < 16; q += 2) {
        ulonglong2 ea = e4[q];
        ulonglong2 eb = e4[q + 1];
        a0 = fma2(ea.x, Mreg[2 * q + 0], a0);
        a1 = fma2(ea.y, Mreg[2 * q + 1], a1);
        a2 = fma2(eb.x, Mreg[2 * q + 2], a2);
        a3 = fma2(eb.y, Mreg[2 * q + 3], a3);
    }
    a0 = add2(a0, a1);
    a2 = add2(a2, a3);
    a0 = add2(a0, a2);
    float2 ac = unpack2(a0);
    return ac.x + ac.y;
}

// ---------- kernels ----------
__global__ void init_kernel(const float* __restrict__ T) {
    int i = blockIdx.x * blockDim.x + threadIdx.x;
    if (i < KK * KK) g_M[i] = expf(T[i]);
}

// 512 CTAs x 64 threads. bid < 256: forward half-chain of batch bid
// (t = 0 .. HALF-1). bid >= 256: backward half-chain of batch bid-256
// (t = 2047 down to HALF-1). Both are the proven R3 loop: exp-domain
// recursion, power-of-2 renormalizer from sA[prev][0]'s exponent
// (bit-identical across threads), PF-deep LDG ring, 1 barrier per step.
__global__ __launch_bounds__(64) void main_kernel(
    const float* __restrict__ scores,
    const float* __restrict__ source,
    const float* __restrict__ sink) {
    __shared__ __align__(16) float sA[2][KK];

    const int bid = blockIdx.x;
    const int j   = threadIdx.x;       // state owned by this thread
    const bool fwd = bid < BB;
    const int b   = fwd ? bid : bid - BB;
    const float* sc = scores + (size_t)b * (SS * KK);

    const float LOG2E = 1.44269504088896340736f;
    int c = 0;

    if (fwd) {
        // Column j of M: Mc[p] = (M[2p][j], M[2p+1][j]).
        unsigned long long Mc[32];
#pragma unroll
        for (int p = 0; p < 32; ++p)
            Mc[p] = pack2(g_M[(2 * p) * KK + j], g_M[(2 * p + 1) * KK + j]);

        float s_ring[PF];
#pragma unroll
        for (int k = 0; k < PF; ++k)
            s_ring[k] = __ldg(&sc[(1 + k) * KK + j]);

        float Acur = exp2f((__ldg(&source[j]) + __ldg(&sc[j])) * LOG2E);
        sA[0][j] = Acur;
        __syncthreads();

#pragma unroll 1
        for (int base = 1; base < HALF; base += PF) {
#pragma unroll
            for (int k = 0; k < PF; ++k) {
                const int t = base + k;
                if (t >= HALF) break;
                const int par = t & 1;

                float es = exp2f(s_ring[k] * LOG2E);
                s_ring[k] = __ldg(&sc[(size_t)(t + PF) * KK + j]);  // <2048, in-bounds

                float A0v = sA[par ^ 1][0];
                int e0 = (int)((__float_as_uint(A0v) >> 23) & 0xFF);
                float scale = __uint_as_float((unsigned)(254 - e0) << 23);
                c += e0 - 127;

                float sum = matvec64(
                    reinterpret_cast<const ulonglong2*>(sA[par ^ 1]), Mc);
                Acur = sum * (es * scale);
                sA[par][j] = Acur;
                __syncthreads();
            }
        }
        g_Af[b * KK + j] = Acur;        // alpha_{HALF-1}, scaled by 2^-c
        if (j == 0) g_cf[b] = c;
    } else {
        // Row j of M: Mr[p] = (M[j][2p], M[j][2p+1]) — contiguous loads.
        unsigned long long Mr[32];
#pragma unroll
        for (int p = 0; p < 32; ++p)
            Mr[p] = pack2(g_M[j * KK + 2 * p], g_M[j * KK + 2 * p + 1]);

        // Bv_t[j] = es_t[j] * beta'_t[j]; iterate Bv_t = es_t o (M Bv_{t+1}),
        // t from 2046 down to HALF; then one final matvec (no es) gives
        // beta'_{HALF-1}. Step v=1..1023 handles t = 2047-v.
        float s_ring[PF];
#pragma unroll
        for (int k = 0; k < PF; ++k)
            s_ring[k] = __ldg(&sc[(size_t)(SS - 2 - k) * KK + j]);

        float Bcur =
            exp2f((__ldg(&sc[(size_t)(SS - 1) * KK + j]) + __ldg(&sink[j])) * LOG2E);
        sA[0][j] = Bcur;
        __syncthreads();

#pragma unroll 1
        for (int base = 1; base < HALF; base += PF) {
#pragma unroll
            for (int k = 0; k < PF; ++k) {
                const int v = base + k;
                if (v >= HALF) break;
                const int par = v & 1;
                const int t = (SS - 1) - v;   // 2046 .. 1024

                float es = exp2f(s_ring[k] * LOG2E);
                s_ring[k] = __ldg(&sc[(size_t)(t - PF) * KK + j]);  // >=1016, in-bounds

                float B0v = sA[par ^ 1][0];
                int e0 = (int)((__float_as_uint(B0v) >> 23) & 0xFF);
                float scale = __uint_as_float((unsigned)(254 - e0) << 23);
                c += e0 - 127;

                float sum = matvec64(
                    reinterpret_cast<const ulonglong2*>(sA[par ^ 1]), Mr);
                Bcur = sum * (es * scale);
                sA[par][j] = Bcur;
                __syncthreads();
            }
        }
        // Final matvec (v=1024, par=0): beta'_{HALF-1} = M * Bv_{HALF}, no es.
        {
            float B0v = sA[1][0];
            int e0 = (int)((__float_as_uint(B0v) >> 23) & 0xFF);
            float scale = __uint_as_float((unsigned)(254 - e0) << 23);
            c += e0 - 127;
            float sum = matvec64(
                reinterpret_cast<const ulonglong2*>(sA[1]), Mr);
            Bcur = sum * scale;
        }
        g_Bb[b * KK + j] = Bcur;        // beta'_{HALF-1}, scaled by 2^-c
        if (j == 0) g_cb[b] = c;
    }
}

// logZ_b = log(sum_j Af[b][j]*Bb[b][j]) + (cf+cb)*ln2
__global__ __launch_bounds__(64) void combine_kernel() {
    __shared__ float sRed[2];
    const int b = blockIdx.x, j = threadIdx.x;
    float v = g_Af[b * KK + j] * g_Bb[b * KK + j];
    float ws = warp_sum(v);
    if ((j & 31) == 0) sRed[j >> 5] = ws;
    __syncthreads();
    if (j == 0) {
        float tot = sRed[0] + sRed[1];
        g_logZ[b] = ((double)log2f(tot) + (double)(g_cf[b] + g_cb[b])) *
                    0.69314718055994530942;
    }
}

__global__ __launch_bounds__(256) void gold_kernel(
    const float* __restrict__ scores,
    const int* __restrict__ states,
    const float* __restrict__ T,
    const float* __restrict__ source,
    const float* __restrict__ sink) {
    __shared__ float red[256];
    const int b = blockIdx.x, tid = threadIdx.x;
    const int*   st = states + (size_t)b * SS;
    const float* sc = scores + (size_t)b * (SS * KK);

    float acc = 0.f;
    for (int t = tid; t < SS; t += 256) {
        int s0 = __ldg(&st[t]);
        acc += __ldg(&sc[t * KK + s0]);
        if (t + 1 < SS) acc += __ldg(&T[s0 * KK + __ldg(&st[t + 1])]);
    }
    red[tid] = acc;
    __syncthreads();
#pragma unroll
    for (int off = 128; off > 0; off >>= 1) {
        if (tid < off) red[tid] += red[tid + off];
        __syncthreads();
    }
    if (tid == 0)
        g_gold[b] = (double)red[0] + (double)__ldg(&source[__ldg(&st[0])]) +
                    (double)__ldg(&sink[__ldg(&st[SS - 1])]);
}

__global__ __launch_bounds__(256) void finalize_kernel(float* __restrict__ out) {
    __shared__ double red[256];
    const int tid = threadIdx.x;
    red[tid] = g_logZ[tid] - g_gold[tid];
    __syncthreads();
#pragma unroll
    for (int off = 128; off > 0; off >>= 1) {
        if (tid < off) red[tid] += red[tid + off];
        __syncthreads();
    }
    if (tid == 0) *out = (float)(red[0] * (1.0 / BB));
}

extern "C" void kernel_launch(void* const* d_in, const int* in_sizes, int n_in,
                              void* d_out, int out_size) {
    const float* scores = (const float*)d_in[0];   // [B,S,K] f32
    const int*   states = (const int*)d_in[1];     // [B,S] i32
    const float* T      = (const float*)d_in[2];   // [K,K] f32
    const float* source = (const float*)d_in[3];   // [K] f32
    const float* sink   = (const float*)d_in[4];   // [K] f32
    float* out = (float*)d_out;

    init_kernel<<<16, 256>>>(T);
    main_kernel<<<2 * BB, 64>>>(scores, source, sink);
    gold_kernel<<<BB, 256>>>(scores, states, T, source, sink);
    combine_kernel<<<BB, 64>>>();
    finalize_kernel<<<1, 256>>>(out);
}

// round 11
// speedup vs baseline: 1.6692x; 1.6692x over previous
#include <cuda_runtime.h>

#define BB 256
#define SS 2048
#define KK 64
#define PF 8      // score prefetch depth (steps)
#define HALF 1024 // steps per half-chain

// Scratch (no allocations allowed in kernel_launch)
__device__ float  g_M[KK * KK];   // exp(transition)
__device__ float  g_Af[BB * KK];  // forward alpha at t=HALF-1 (scaled)
__device__ float  g_Bb[BB * KK];  // backward beta' at t=HALF-1 (scaled)
__device__ int    g_cf[BB];       // forward exponent offset (log2 units)
__device__ int    g_cb[BB];       // backward exponent offset
__device__ double g_logZ[BB];
__device__ double g_gold[BB];

// ---------- packed f32x2 helpers (Blackwell FFMA2 path, PTX-only) ----------
__device__ __forceinline__ unsigned long long fma2(unsigned long long a,
                                                   unsigned long long b,
                                                   unsigned long long c) {
    unsigned long long d;
    asm("fma.rn.f32x2 %0, %1, %2, %3;" : "=l"(d) : "l"(a), "l"(b), "l"(c));
    return d;
}
__device__ __forceinline__ unsigned long long add2(unsigned long long a,
                                                   unsigned long long b) {
    unsigned long long d;
    asm("add.rn.f32x2 %0, %1, %2;" : "=l"(d) : "l"(a), "l"(b));
    return d;
}
__device__ __forceinline__ float2 unpack2(unsigned long long v) {
    float2 r;
    asm("mov.b64 {%0, %1}, %2;" : "=f"(r.x), "=f"(r.y) : "l"(v));
    return r;
}
__device__ __forceinline__ unsigned long long pack2(float lo, float hi) {
    unsigned long long r;
    asm("mov.b64 %0, {%1, %2};" : "=l"(r) : "f"(lo), "f"(hi));
    return r;
}
__device__ __forceinline__ float warp_sum(float v) {
#pragma unroll
    for (int o = 16; o > 0; o >>= 1)
        v += __shfl_xor_sync(0xffffffffu, v, o);
    return v;
}

// 64-wide matvec partial: sum_i A[i]*Mreg[i] (paired), 4 accumulator chains.
__device__ __forceinline__ float matvec64(const ulonglong2* e4,
                                          const unsigned long long* Mreg) {
    unsigned long long a0 = 0ull, a1 = 0ull, a2 = 0ull, a3 = 0ull;
#pragma unroll
    for (int q = 0; q < 16; q += 2) {
        ulonglong2 ea = e4[q];
        ulonglong2 eb = e4[q + 1];
        a0 = fma2(ea.x, Mreg[2 * q + 0], a0);
        a1 = fma2(ea.y, Mreg[2 * q + 1], a1);
        a2 = fma2(eb.x, Mreg[2 * q + 2], a2);
        a3 = fma2(eb.y, Mreg[2 * q + 3], a3);
    }
    a0 = add2(a0, a1);
    a2 = add2(a2, a3);
    a0 = add2(a0, a2);
    float2 ac = unpack2(a0);
    return ac.x + ac.y;
}

// ---------- kernels ----------
__global__ void init_kernel(const float* __restrict__ T) {
    int i = blockIdx.x * blockDim.x + threadIdx.x;
    if (i < KK * KK) g_M[i] = expf(T[i]);
}

// 256 CTAs x 128 threads. Chain 0 (warps 0/1, SMSP 0/1) = forward half of
// batch b; chain 1 (warps 2/3, SMSP 2/3) = backward half of the SAME batch.
// All 4 SMSPs carry work; ~1.73 CTAs/SM so co-resident CTAs hide the serial
// per-step latency. ONE unified unrolled loop serves both directions
// (direction enters only through the score-row index and which slice of M
// lives in registers), keeping the I-footprint single-copy.
__global__ __launch_bounds__(128) void main_kernel(
    const float* __restrict__ scores,
    const float* __restrict__ source,
    const float* __restrict__ sink) {
    __shared__ __align__(16) float sA[2][2][KK];  // [chain][parity][state]

    const int chain = threadIdx.x >> 6;   // 0 = forward, 1 = backward
    const int j     = threadIdx.x & 63;   // state owned by this thread
    const int b     = blockIdx.x;
    const float* sc = scores + (size_t)b * (SS * KK);
    const bool fwd  = (chain == 0);

    const float LOG2E = 1.44269504088896340736f;

    // M slice in registers: forward needs column j (stride KK), backward
    // needs row j (stride 1). Mreg[p] pairs elements 2p, 2p+1.
    const int m0 = fwd ? j : j * KK;
    const int ms = fwd ? KK : 1;
    unsigned long long Mreg[32];
#pragma unroll
    for (int p = 0; p < 32; ++p)
        Mreg[p] = pack2(g_M[m0 + (2 * p) * ms], g_M[m0 + (2 * p + 1) * ms]);

    // Direction: step v uses score row t0 + sgn*v.
    const int t0  = fwd ? 0 : SS - 1;
    const int sgn = fwd ? 1 : -1;

    // Score prefetch ring: slot k holds the row for step v with (v-1)%PF == k.
    float s_ring[PF];
#pragma unroll
    for (int k = 0; k < PF; ++k)
        s_ring[k] = __ldg(&sc[(size_t)(t0 + sgn * (1 + k)) * KK + j]);

    // Init: fwd A_0 = exp(source + s_0); bwd Bv_{2047} = exp(sink + s_2047).
    float bnd  = fwd ? __ldg(&source[j]) : __ldg(&sink[j]);
    float Acur = exp2f((bnd + __ldg(&sc[(size_t)t0 * KK + j])) * LOG2E);
    int c = 0;
    sA[chain][0][j] = Acur;
    __syncthreads();

#pragma unroll 1
    for (int base = 1; base < HALF; base += PF) {
#pragma unroll
        for (int k = 0; k < PF; ++k) {
            const int v   = base + k;        // 1..HALF-1 (HALF%PF==0... v<HALF+PF-? )
            const int par = v & 1;

            // es for this step (row loaded PF steps ago); refill in-bounds:
            // fwd max row v+PF <= 1031 < 2048; bwd min row >= 1016 >= 0.
            float es = exp2f(s_ring[k] * LOG2E);
            s_ring[k] = __ldg(&sc[(size_t)(t0 + sgn * (v + PF)) * KK + j]);

            // Consistent power-of-2 rescale from exponent of prev[0]
            // (same shared word on every thread of the chain).
            float A0v = sA[chain][par ^ 1][0];
            int e0 = (int)((__float_as_uint(A0v) >> 23) & 0xFF);
            float scale = __uint_as_float((unsigned)(254 - e0) << 23);
            c += e0 - 127;

            float sum = matvec64(
                reinterpret_cast<const ulonglong2*>(sA[chain][par ^ 1]), Mreg);
            Acur = sum * (es * scale);
            sA[chain][par][j] = Acur;
            __syncthreads();
        }
    }
    // Loop ran v = 1..HALF-1 exactly (HALF-1 = 1023, last par = 1).

    if (fwd) {
        g_Af[b * KK + j] = Acur;          // alpha_{1023}, scaled 2^-c
        if (j == 0) g_cf[b] = c;
    } else {
        // beta'_{1023} = M * Bv_{1024} (no es), one extra renormalized matvec.
        float B0v = sA[chain][1][0];
        int e0 = (int)((__float_as_uint(B0v) >> 23) & 0xFF);
        float scale = __uint_as_float((unsigned)(254 - e0) << 23);
        c += e0 - 127;
        float sum = matvec64(
            reinterpret_cast<const ulonglong2*>(sA[chain][1]), Mreg);
        g_Bb[b * KK + j] = sum * scale;   // beta'_{1023}, scaled 2^-c
        if (j == 0) g_cb[b] = c;
    }
}

// logZ_b = log(sum_j Af[b][j]*Bb[b][j]) + (cf+cb)*ln2
__global__ __launch_bounds__(64) void combine_kernel() {
    __shared__ float sRed[2];
    const int b = blockIdx.x, j = threadIdx.x;
    float v = g_Af[b * KK + j] * g_Bb[b * KK + j];
    float ws = warp_sum(v);
    if ((j & 31) == 0) sRed[j >> 5] = ws;
    __syncthreads();
    if (j == 0) {
        float tot = sRed[0] + sRed[1];
        g_logZ[b] = ((double)log2f(tot) + (double)(g_cf[b] + g_cb[b])) *
                    0.69314718055994530942;
    }
}

__global__ __launch_bounds__(256) void gold_kernel(
    const float* __restrict__ scores,
    const int* __restrict__ states,
    const float* __restrict__ T,
    const float* __restrict__ source,
    const float* __restrict__ sink) {
    __shared__ float red[256];
    const int b = blockIdx.x, tid = threadIdx.x;
    const int*   st = states + (size_t)b * SS;
    const float* sc = scores + (size_t)b * (SS * KK);

    float acc = 0.f;
    for (int t = tid; t < SS; t += 256) {
        int s0 = __ldg(&st[t]);
        acc += __ldg(&sc[t * KK + s0]);
        if (t + 1 < SS) acc += __ldg(&T[s0 * KK + __ldg(&st[t + 1])]);
    }
    red[tid] = acc;
    __syncthreads();
#pragma unroll
    for (int off = 128; off > 0; off >>= 1) {
        if (tid < off) red[tid] += red[tid + off];
        __syncthreads();
    }
    if (tid == 0)
        g_gold[b] = (double)red[0] + (double)__ldg(&source[__ldg(&st[0])]) +
                    (double)__ldg(&sink[__ldg(&st[SS - 1])]);
}

__global__ __launch_bounds__(256) void finalize_kernel(float* __restrict__ out) {
    __shared__ double red[256];
    const int tid = threadIdx.x;
    red[tid] = g_logZ[tid] - g_gold[tid];
    __syncthreads();
#pragma unroll
    for (int off = 128; off > 0; off >>= 1) {
        if (tid < off) red[tid] += red[tid + off];
        __syncthreads();
    }
    if (tid == 0) *out = (float)(red[0] * (1.0 / BB));
}

extern "C" void kernel_launch(void* const* d_in, const int* in_sizes, int n_in,
                              void* d_out, int out_size) {
    const float* scores = (const float*)d_in[0];   // [B,S,K] f32
    const int*   states = (const int*)d_in[1];     // [B,S] i32
    const float* T      = (const float*)d_in[2];   // [K,K] f32
    const float* source = (const float*)d_in[3];   // [K] f32
    const float* sink   = (const float*)d_in[4];   // [K] f32
    float* out = (float*)d_out;

    init_kernel<<<16, 256>>>(T);
    main_kernel<<<BB, 128>>>(scores, source, sink);
    gold_kernel<<<BB, 256>>>(scores, states, T, source, sink);
    combine_kernel<<<BB, 64>>>();
    finalize_kernel<<<1, 256>>>(out);
}